// round 15
// baseline (speedup 1.0000x reference)
#include <cuda_runtime.h>
#include <cstdint>

#define BATCH 4
#define S_LEN 2048
#define EMB   1024
#define NH    16
#define DH    64

// Scratch (allocation-free rule: __device__ globals). bf16 hi/lo planes,
// stored COLUMN-PERMUTED within each 16-element k-group:
//   memory order = [0,1,8,9, 2,3,10,11, 4,5,12,13, 6,7,14,15]
// so each MMA fragment (k=2q,2q+1,2q+8,2q+9) is one contiguous LDS.64.
__device__ uint16_t g_Xh[8388608], g_Xl[8388608];   // X  [8192,1024]
__device__ uint16_t g_Wh[4194304], g_Wl[4194304];   // Wq,Wk,Wv,Wo
__device__ uint16_t g_Qh[8388608], g_Ql[8388608];   // Q  (x0.125 folded)
__device__ uint16_t g_Kh[8388608], g_Kl[8388608];   // K
__device__ float    g_V [8388608];                  // V  tf32-rounded fp32
__device__ uint16_t g_Yh[8388608], g_Yl[8388608];   // Y  [B,S,E]

// ===========================================================================
// Helpers
// ===========================================================================
__device__ __forceinline__ uint32_t smem_u32(const void* p) {
    uint32_t a;
    asm("{ .reg .u64 t; cvta.to.shared.u64 t, %1; cvt.u32.u64 %0, t; }"
        : "=r"(a) : "l"(p));
    return a;
}
__device__ __forceinline__ void cp_async16(uint32_t s, const void* g) {
    asm volatile("cp.async.cg.shared.global [%0], [%1], 16;" :: "r"(s), "l"(g));
}
__device__ __forceinline__ void cp_commit() {
    asm volatile("cp.async.commit_group;" ::: "memory");
}
template <int N>
__device__ __forceinline__ void cp_wait_group() {
    asm volatile("cp.async.wait_group %0;" :: "n"(N) : "memory");
}
__device__ __forceinline__ void mma_bf16(float* c, const uint32_t* a, const uint32_t* b) {
    asm volatile(
        "mma.sync.aligned.m16n8k16.row.col.f32.bf16.bf16.f32 "
        "{%0,%1,%2,%3}, {%4,%5,%6,%7}, {%8,%9}, {%0,%1,%2,%3};"
        : "+f"(c[0]), "+f"(c[1]), "+f"(c[2]), "+f"(c[3])
        : "r"(a[0]), "r"(a[1]), "r"(a[2]), "r"(a[3]), "r"(b[0]), "r"(b[1]));
}
__device__ __forceinline__ void mma_tf32(float* c, const uint32_t* a, const uint32_t* b) {
    asm volatile(
        "mma.sync.aligned.m16n8k8.row.col.f32.tf32.tf32.f32 "
        "{%0,%1,%2,%3}, {%4,%5,%6,%7}, {%8,%9}, {%0,%1,%2,%3};"
        : "+f"(c[0]), "+f"(c[1]), "+f"(c[2]), "+f"(c[3])
        : "r"(a[0]), "r"(a[1]), "r"(a[2]), "r"(a[3]), "r"(b[0]), "r"(b[1]));
}
__device__ __forceinline__ uint32_t f2tf32(float x) {
    uint32_t r;
    asm("cvt.rna.tf32.f32 %0, %1;" : "=r"(r) : "f"(x));
    return r;
}
__device__ __forceinline__ float rtf(float x) { return __uint_as_float(f2tf32(x)); }

// bf16 split via integer bit ops (RN); lo is an unfoldable exact FSUB.
__device__ __forceinline__ uint32_t bf_rn_bits(float x) {
    const uint32_t b = __float_as_uint(x);
    return (b + 0x7FFFu + ((b >> 16) & 1u)) & 0xFFFF0000u;
}
__device__ __forceinline__ void bf_split(float x, uint16_t& h, uint16_t& l) {
    const uint32_t hb = bf_rn_bits(x);
    h = (uint16_t)(hb >> 16);
    const float lo = x - __uint_as_float(hb);
    l = (uint16_t)(bf_rn_bits(lo) >> 16);
}
// permuted slot (element units) for an even pair base c within its 16-group
__device__ __forceinline__ int perm_pair(int c) {
    return (c & ~15) + (((c >> 1) & 3) << 2) + (((c >> 3) & 1) << 1);
}

// ===========================================================================
// Pre-split fp32 -> bf16 hi/lo planes, column-permuted within 16-groups.
// Thread i handles cols 4i..4i+3 (two even pairs); pair c0 -> slot m0,
// pair c0+2 -> slot m0+4.
// ===========================================================================
__global__ __launch_bounds__(256) void split_bf(const float4* __restrict__ src,
                                                uint16_t* __restrict__ dh,
                                                uint16_t* __restrict__ dl, int n4)
{
    const int i = blockIdx.x * 256 + threadIdx.x;
    if (i >= n4) return;
    const float4 v = src[i];
    uint16_t h0, h1, h2, h3, l0, l1, l2, l3;
    bf_split(v.x, h0, l0); bf_split(v.y, h1, l1);
    bf_split(v.z, h2, l2); bf_split(v.w, h3, l3);
    const int c0 = (4 * i) & 15;                       // 0,4,8,12
    const int g  = (4 * i) & ~15;                      // group base (global)
    const int m0 = g + (((c0 & 4) << 1) | ((c0 & 8) >> 2));
    *(uint32_t*)&dh[m0]     = (uint32_t)h0 | ((uint32_t)h1 << 16);
    *(uint32_t*)&dh[m0 + 4] = (uint32_t)h2 | ((uint32_t)h3 << 16);
    *(uint32_t*)&dl[m0]     = (uint32_t)l0 | ((uint32_t)l1 << 16);
    *(uint32_t*)&dl[m0 + 4] = (uint32_t)l2 | ((uint32_t)l3 << 16);
}

// ===========================================================================
// 3xbf16 GEMM, permuted planes, LDS.64 fragments. Pitch 96 B/row
// (conflict-free LDS.64: bank bases {0,24,16,8} per half-warp phase).
// Stage = 4 planes x 12288 = 49152 B; 2 stages = 98304 B (2 CTAs/SM).
// ===========================================================================
#define GPIT   96
#define GPLANE (128 * GPIT)              // 12288
#define GSTG   (4 * GPLANE)              // 49152
#define GSMEM2 (2 * GSTG)                // 98304

template <bool SCATTER>
__global__ __launch_bounds__(256, 2) void gemm_bf(float* __restrict__ outp)
{
    const uint16_t *Aph, *Apl, *Bph, *Bpl;
    if (SCATTER) {
        Aph = g_Xh; Apl = g_Xl;
        Bph = g_Wh + (size_t)blockIdx.z * 1048576;
        Bpl = g_Wl + (size_t)blockIdx.z * 1048576;
    } else {
        Aph = g_Yh; Apl = g_Yl;
        Bph = g_Wh + 3145728; Bpl = g_Wl + 3145728;
    }

    extern __shared__ __align__(16) char smc[];
    const int tid  = threadIdx.x;
    const int wid  = tid >> 5;
    const int lane = tid & 31;
    const int m0   = blockIdx.x * 128;
    const int n0   = blockIdx.y * 128;
    const int wm   = (wid >> 1) * 32;
    const int wn   = (wid & 1) * 64;
    const int q    = lane & 3;
    const int g8   = lane >> 2;
    const uint32_t sbase = smem_u32(smc);

    auto load_stage = [&](int kt, uint32_t soff) {
#pragma unroll
        for (int j = 0; j < 4; j++) {
            const int f = tid + 256 * j;
            const int pl = f >> 9, r = (f >> 2) & 127, c = f & 3;
            const uint16_t* ap = pl ? Apl : Aph;
            cp_async16(sbase + soff + (uint32_t)(pl * GPLANE + r * GPIT + c * 16),
                       ap + ((size_t)(m0 + r)) * 1024 + kt * 32 + c * 8);
        }
#pragma unroll
        for (int j = 0; j < 4; j++) {
            const int f = tid + 256 * j;
            const int pl = f >> 9, r = (f >> 2) & 127, c = f & 3;
            const uint16_t* bp = pl ? Bpl : Bph;
            cp_async16(sbase + soff + (uint32_t)(2 * GPLANE + pl * GPLANE + r * GPIT + c * 16),
                       bp + ((size_t)(n0 + r)) * 1024 + kt * 32 + c * 8);
        }
        cp_commit();
    };

    load_stage(0, 0);

    float acc[2][8][4];
#pragma unroll
    for (int t = 0; t < 2; t++)
#pragma unroll
        for (int u = 0; u < 8; u++)
#pragma unroll
            for (int r = 0; r < 4; r++) acc[t][u][r] = 0.f;

    for (int kt = 0; kt < 32; kt++) {
        if (kt + 1 < 32) {
            load_stage(kt + 1, ((kt + 1) & 1) * (uint32_t)GSTG);
            cp_wait_group<1>();
        } else {
            cp_wait_group<0>();
        }
        __syncthreads();

        const char* stg = smc + (kt & 1) * GSTG;
        const char* Ah = stg;
        const char* Al = stg + GPLANE;
        const char* Bh = stg + 2 * GPLANE;
        const char* Bl = stg + 3 * GPLANE;

#pragma unroll
        for (int ks = 0; ks < 2; ks++) {
            const int kb = ks * 32 + 8 * q;          // permuted: LDS.64 offset
            uint32_t ah[2][4], al[2][4];
#pragma unroll
            for (int t = 0; t < 2; t++) {
                const int r0 = (wm + t * 16 + g8) * GPIT;
                const uint2 vh0 = *(const uint2*)(Ah + r0 + kb);
                const uint2 vh1 = *(const uint2*)(Ah + r0 + 8 * GPIT + kb);
                const uint2 vl0 = *(const uint2*)(Al + r0 + kb);
                const uint2 vl1 = *(const uint2*)(Al + r0 + 8 * GPIT + kb);
                ah[t][0] = vh0.x; ah[t][2] = vh0.y;
                ah[t][1] = vh1.x; ah[t][3] = vh1.y;
                al[t][0] = vl0.x; al[t][2] = vl0.y;
                al[t][1] = vl1.x; al[t][3] = vl1.y;
            }
#pragma unroll
            for (int u = 0; u < 8; u++) {
                const int nb = (wn + u * 8 + g8) * GPIT + kb;
                const uint2 vbh = *(const uint2*)(Bh + nb);
                const uint2 vbl = *(const uint2*)(Bl + nb);
                uint32_t bh[2], bl[2];
                bh[0] = vbh.x; bh[1] = vbh.y;
                bl[0] = vbl.x; bl[1] = vbl.y;
#pragma unroll
                for (int t = 0; t < 2; t++) {
                    mma_bf16(acc[t][u], ah[t], bh);
                    mma_bf16(acc[t][u], ah[t], bl);
                    mma_bf16(acc[t][u], al[t], bh);
                }
            }
        }
        __syncthreads();    // all reads done before next stage overwrite
    }

    // ---- epilogue ----
    const int z = SCATTER ? blockIdx.z : 3;
#pragma unroll
    for (int t = 0; t < 2; t++) {
#pragma unroll
        for (int u = 0; u < 8; u++) {
            const int m = m0 + wm + t * 16 + g8;
            const int n = n0 + wn + u * 8 + q * 2;
#pragma unroll
            for (int hh = 0; hh < 2; hh++) {
                const int mm = m + hh * 8;
                const float v0 = acc[t][u][hh * 2];
                const float v1 = acc[t][u][hh * 2 + 1];
                if (SCATTER) {
                    const int bb = mm >> 11, s = mm & 2047;
                    const int h = n >> 6, d0 = n & 63;
                    const size_t rowb = (((size_t)bb * NH + h) * S_LEN + s) * DH;
                    if (z == 0) {
                        const float y0 = v0 * 0.125f, y1 = v1 * 0.125f; // exact fold
                        uint16_t h0, l0, h1, l1;
                        bf_split(y0, h0, l0); bf_split(y1, h1, l1);
                        const size_t e = rowb + perm_pair(d0);
                        *(uint32_t*)&g_Qh[e] = (uint32_t)h0 | ((uint32_t)h1 << 16);
                        *(uint32_t*)&g_Ql[e] = (uint32_t)l0 | ((uint32_t)l1 << 16);
                    } else if (z == 1) {
                        uint16_t h0, l0, h1, l1;
                        bf_split(v0, h0, l0); bf_split(v1, h1, l1);
                        const size_t e = rowb + perm_pair(d0);
                        *(uint32_t*)&g_Kh[e] = (uint32_t)h0 | ((uint32_t)h1 << 16);
                        *(uint32_t*)&g_Kl[e] = (uint32_t)l0 | ((uint32_t)l1 << 16);
                    } else {
                        *(float2*)(g_V + rowb + d0) = make_float2(rtf(v0), rtf(v1));
                    }
                } else {
                    *(float2*)(outp + (size_t)mm * EMB + n) = make_float2(v0, v1);
                }
            }
        }
    }
}

// ===========================================================================
// Flash attention: 3xbf16 QK (permuted planes, LDS.64 frags, pitch 160 B:
// conflict-free bank bases {0,8,16,24}), 1xTF32 PV, race-fixed, LPT.
// SMEM: Q planes 2x20480 (P fp32 pitch-68 overlays) | K 2st x (2x10240) | V 2x18432
//      = 40960 + 40960 + 36864 = 118784 B (flash is reg-limited to 1 CTA/SM).
// ===========================================================================
#define FQPIT 160
#define FQPL  20480                       // 128*160
#define FKPL  10240                       // 64*160
#define FKBASE 40960
#define FVBASE 81920
#define FLASH_SMEM 118784

__global__ __launch_bounds__(256) void flash_mma()
{
    const int bh = blockIdx.x;
    const int qi = 15 - blockIdx.y;          // LPT: long jobs first

    extern __shared__ __align__(16) char smc[];
    float* P = (float*)smc;                   // pitch 68 floats, overlays Q planes

    const int tid  = threadIdx.x;
    const int wid  = tid >> 5;
    const int lane = tid & 31;
    const int g8   = lane >> 2;
    const int q    = lane & 3;
    const int wm   = wid * 16;
    const uint32_t sbase = smem_u32(smc);

    // ---- Q planes (group 0) ----
#pragma unroll
    for (int j = 0; j < 8; j++) {
        const int f = tid + 256 * j;
        const int pl = f >> 10, ff = f & 1023, row = ff >> 3, c = ff & 7;
        const uint16_t* qp = pl ? g_Ql : g_Qh;
        cp_async16(sbase + (uint32_t)(pl * FQPL + row * FQPIT + c * 16),
                   qp + ((size_t)bh * S_LEN + qi * 128 + row) * 64 + c * 8);
    }
    cp_commit();
    // ---- K planes + V, stage 0 (group 1) ----
#pragma unroll
    for (int j = 0; j < 4; j++) {
        const int f = tid + 256 * j;
        const int pl = f >> 9, ff = f & 511, row = ff >> 3, c = ff & 7;
        const uint16_t* kp = pl ? g_Kl : g_Kh;
        cp_async16(sbase + (uint32_t)(FKBASE + pl * FKPL + row * FQPIT + c * 16),
                   kp + ((size_t)bh * S_LEN + row) * 64 + c * 8);
    }
#pragma unroll
    for (int j = 0; j < 4; j++) {
        const int f = tid + 256 * j;
        const int row = f >> 4, c = f & 15;
        cp_async16(sbase + (uint32_t)(FVBASE + row * 288 + c * 16),
                   g_V + ((size_t)bh * S_LEN + row) * 64 + c * 4);
    }
    cp_commit();

    cp_wait_group<1>();
    __syncthreads();

    // ---- hoist Q fragments (LDS.64 per pair-group) ----
    uint32_t qh[4][4], ql[4][4];
    {
        const char* Qhp = smc;
        const char* Qlp = smc + FQPL;
        const int rb = (wm + g8) * FQPIT;
#pragma unroll
        for (int kc = 0; kc < 4; kc++) {
            const int kb = kc * 32 + 8 * q;
            const uint2 vh0 = *(const uint2*)(Qhp + rb + kb);
            const uint2 vh1 = *(const uint2*)(Qhp + rb + 8 * FQPIT + kb);
            const uint2 vl0 = *(const uint2*)(Qlp + rb + kb);
            const uint2 vl1 = *(const uint2*)(Qlp + rb + 8 * FQPIT + kb);
            qh[kc][0] = vh0.x; qh[kc][2] = vh0.y;
            qh[kc][1] = vh1.x; qh[kc][3] = vh1.y;
            ql[kc][0] = vl0.x; ql[kc][2] = vl0.y;
            ql[kc][1] = vl1.x; ql[kc][3] = vl1.y;
        }
    }
    __syncthreads();                          // Q reads done before P stores

    float m0 = -1e30f, m1 = -1e30f, l0 = 0.f, l1 = 0.f;
    float o[8][4];
#pragma unroll
    for (int u = 0; u < 8; u++)
#pragma unroll
        for (int r = 0; r < 4; r++) o[u][r] = 0.f;

    const int row0 = qi * 128 + wm + g8;
    const int row1 = row0 + 8;
    const int last = 2 * qi + 1;

    for (int kt = 0; kt <= last; kt++) {
        if (kt < last) {
            const int st = (kt + 1) & 1;
            const size_t kbase = (size_t)bh * S_LEN + (size_t)(kt + 1) * 64;
#pragma unroll
            for (int j = 0; j < 4; j++) {
                const int f = tid + 256 * j;
                const int pl = f >> 9, ff = f & 511, row = ff >> 3, c = ff & 7;
                const uint16_t* kp = pl ? g_Kl : g_Kh;
                cp_async16(sbase + (uint32_t)(FKBASE + st * 2 * FKPL + pl * FKPL + row * FQPIT + c * 16),
                           kp + (kbase + row) * 64 + c * 8);
            }
#pragma unroll
            for (int j = 0; j < 4; j++) {
                const int f = tid + 256 * j;
                const int row = f >> 4, c = f & 15;
                cp_async16(sbase + (uint32_t)(FVBASE + st * 18432 + row * 288 + c * 16),
                           g_V + (kbase + row) * 64 + c * 4);
            }
            cp_commit();
            cp_wait_group<1>();
        } else {
            cp_wait_group<0>();
        }
        __syncthreads();

        const char* Khp = smc + FKBASE + (kt & 1) * 2 * FKPL;
        const char* Klp = Khp + FKPL;
        const float* Vst = (const float*)(smc + FVBASE + (kt & 1) * 18432);

        // ---- S = Q K^T (3xbf16, LDS.64 B-frags) ----
        float s[8][4];
#pragma unroll
        for (int u = 0; u < 8; u++)
#pragma unroll
            for (int r = 0; r < 4; r++) s[u][r] = 0.f;

#pragma unroll
        for (int kc = 0; kc < 4; kc++) {
#pragma unroll
            for (int u = 0; u < 8; u++) {
                const int nb = (u * 8 + g8) * FQPIT + kc * 32 + 8 * q;
                const uint2 vh = *(const uint2*)(Khp + nb);
                const uint2 vl = *(const uint2*)(Klp + nb);
                uint32_t bh2[2], bl2[2];
                bh2[0] = vh.x; bh2[1] = vh.y;
                bl2[0] = vl.x; bl2[1] = vl.y;
                mma_bf16(s[u], qh[kc], bh2);
                mma_bf16(s[u], qh[kc], bl2);
                mma_bf16(s[u], ql[kc], bh2);
            }
        }

        // causal mask (diagonal tiles only)
        if (kt >= 2 * qi) {
            const int cb = kt * 64;
#pragma unroll
            for (int u = 0; u < 8; u++) {
                const int c = cb + u * 8 + 2 * q;
                if (c     > row0) s[u][0] = -1e30f;
                if (c + 1 > row0) s[u][1] = -1e30f;
                if (c     > row1) s[u][2] = -1e30f;
                if (c + 1 > row1) s[u][3] = -1e30f;
            }
        }

        // ---- online softmax (quad reduction) ----
        float tm0 = -1e30f, tm1 = -1e30f;
#pragma unroll
        for (int u = 0; u < 8; u++) {
            tm0 = fmaxf(tm0, fmaxf(s[u][0], s[u][1]));
            tm1 = fmaxf(tm1, fmaxf(s[u][2], s[u][3]));
        }
        tm0 = fmaxf(tm0, __shfl_xor_sync(0xffffffffu, tm0, 1));
        tm0 = fmaxf(tm0, __shfl_xor_sync(0xffffffffu, tm0, 2));
        tm1 = fmaxf(tm1, __shfl_xor_sync(0xffffffffu, tm1, 1));
        tm1 = fmaxf(tm1, __shfl_xor_sync(0xffffffffu, tm1, 2));

        const float mn0 = fmaxf(m0, tm0);
        const float mn1 = fmaxf(m1, tm1);
        const float a0 = __expf(m0 - mn0);
        const float a1 = __expf(m1 - mn1);

        float ps0 = 0.f, ps1 = 0.f;
#pragma unroll
        for (int u = 0; u < 8; u++) {
            const float p00 = __expf(s[u][0] - mn0);
            const float p01 = __expf(s[u][1] - mn0);
            const float p10 = __expf(s[u][2] - mn1);
            const float p11 = __expf(s[u][3] - mn1);
            ps0 += p00 + p01;
            ps1 += p10 + p11;
            *(float2*)&P[(wm + g8) * 68 + u * 8 + 2 * q]     = make_float2(p00, p01);
            *(float2*)&P[(wm + g8 + 8) * 68 + u * 8 + 2 * q] = make_float2(p10, p11);
        }
        ps0 += __shfl_xor_sync(0xffffffffu, ps0, 1);
        ps0 += __shfl_xor_sync(0xffffffffu, ps0, 2);
        ps1 += __shfl_xor_sync(0xffffffffu, ps1, 1);
        ps1 += __shfl_xor_sync(0xffffffffu, ps1, 2);

        l0 = l0 * a0 + ps0;
        l1 = l1 * a1 + ps1;
        m0 = mn0;
        m1 = mn1;
#pragma unroll
        for (int u = 0; u < 8; u++) {
            o[u][0] *= a0; o[u][1] *= a0;
            o[u][2] *= a1; o[u][3] *= a1;
        }
        __syncwarp();   // P visible within warp

        // ---- O += P @ V (1xTF32; V pre-rounded) ----
#pragma unroll
        for (int kc = 0; kc < 8; kc++) {
            uint32_t a[4];
            a[0] = f2tf32(P[(wm + g8) * 68 + kc * 8 + q]);
            a[1] = f2tf32(P[(wm + g8 + 8) * 68 + kc * 8 + q]);
            a[2] = f2tf32(P[(wm + g8) * 68 + kc * 8 + q + 4]);
            a[3] = f2tf32(P[(wm + g8 + 8) * 68 + kc * 8 + q + 4]);
#pragma unroll
            for (int u = 0; u < 8; u++) {
                uint32_t b[2];
                b[0] = __float_as_uint(Vst[(kc * 8 + q) * 72 + u * 8 + g8]);
                b[1] = __float_as_uint(Vst[(kc * 8 + q + 4) * 72 + u * 8 + g8]);
                mma_tf32(o[u], a, b);
            }
        }

        __syncthreads();   // RACE FIX: all warps done reading stage kt&1
                           // before anyone issues next cp.async into it
    }

    // ---- epilogue: normalize, write Y as permuted bf16 planes ----
    const int b = bh >> 4, h = bh & 15;
    const float i0 = 1.0f / l0;
    const float i1 = 1.0f / l1;
#pragma unroll
    for (int u = 0; u < 8; u++) {
        const int c = u * 8 + 2 * q;
        const int mp = perm_pair(c);
        const size_t e0 = ((size_t)b * S_LEN + row0) * EMB + h * 64 + mp;
        const size_t e1 = ((size_t)b * S_LEN + row1) * EMB + h * 64 + mp;
        const float y0 = o[u][0] * i0, y1 = o[u][1] * i0;
        const float y2 = o[u][2] * i1, y3 = o[u][3] * i1;
        uint16_t h0, lo0, h1, lo1, h2, lo2, h3, lo3;
        bf_split(y0, h0, lo0); bf_split(y1, h1, lo1);
        bf_split(y2, h2, lo2); bf_split(y3, h3, lo3);
        *(uint32_t*)&g_Yh[e0] = (uint32_t)h0 | ((uint32_t)h1 << 16);
        *(uint32_t*)&g_Yl[e0] = (uint32_t)lo0 | ((uint32_t)lo1 << 16);
        *(uint32_t*)&g_Yh[e1] = (uint32_t)h2 | ((uint32_t)h3 << 16);
        *(uint32_t*)&g_Yl[e1] = (uint32_t)lo2 | ((uint32_t)lo3 << 16);
    }
}

// ---------------------------------------------------------------------------
extern "C" void kernel_launch(void* const* d_in, const int* in_sizes, int n_in,
                              void* d_out, int out_size)
{
    (void)in_sizes; (void)n_in; (void)out_size;
    const float* x  = (const float*)d_in[0];
    const float* Wq = (const float*)d_in[1];
    const float* Wk = (const float*)d_in[2];
    const float* Wv = (const float*)d_in[3];
    const float* Wo = (const float*)d_in[4];
    float* out = (float*)d_out;

    static bool attr_done = false;       // idempotent setup (not a work guard)
    static uint16_t *pXh, *pXl, *pWh, *pWl;
    if (!attr_done) {
        cudaFuncSetAttribute(gemm_bf<true>,
                             cudaFuncAttributeMaxDynamicSharedMemorySize, GSMEM2);
        cudaFuncSetAttribute(gemm_bf<false>,
                             cudaFuncAttributeMaxDynamicSharedMemorySize, GSMEM2);
        cudaFuncSetAttribute(flash_mma,
                             cudaFuncAttributeMaxDynamicSharedMemorySize, FLASH_SMEM);
        cudaGetSymbolAddress((void**)&pXh, g_Xh);
        cudaGetSymbolAddress((void**)&pXl, g_Xl);
        cudaGetSymbolAddress((void**)&pWh, g_Wh);
        cudaGetSymbolAddress((void**)&pWl, g_Wl);
        attr_done = true;
    }

    // 0) split X and weights into permuted bf16 hi/lo planes
    split_bf<<<8192, 256>>>((const float4*)x,  pXh, pXl, 2097152);
    split_bf<<<1024, 256>>>((const float4*)Wq, pWh,           pWl,           262144);
    split_bf<<<1024, 256>>>((const float4*)Wk, pWh + 1048576, pWl + 1048576, 262144);
    split_bf<<<1024, 256>>>((const float4*)Wv, pWh + 2097152, pWl + 2097152, 262144);
    split_bf<<<1024, 256>>>((const float4*)Wo, pWh + 3145728, pWl + 3145728, 262144);
    // 1) QKV projections (3xbf16, LDS.64 fragments)
    gemm_bf<true><<<dim3(64, 8, 3), 256, GSMEM2>>>(nullptr);
    // 2) Causal flash attention (3xbf16 QK LDS.64, 1xTF32 PV, race-fixed, LPT)
    flash_mma<<<dim3(64, 16), 256, FLASH_SMEM>>>();
    // 3) Output projection (3xbf16)
    gemm_bf<false><<<dim3(64, 8), 256, GSMEM2>>>(out);
}

// round 16
// speedup vs baseline: 1.0762x; 1.0762x over previous
#include <cuda_runtime.h>
#include <cstdint>

#define BATCH 4
#define S_LEN 2048
#define EMB   1024
#define NH    16
#define DH    64

// Scratch (allocation-free rule: __device__ globals). bf16 hi/lo planes.
// X, W, Y planes are COLUMN-PERMUTED within each 16-element k-group
//   (memory order [0,1,8,9, 2,3,10,11, 4,5,12,13, 6,7,14,15]) so the gemm
//   loads each MMA fragment with one LDS.64.
// Q, K planes are LINEAR (round-14 flash contract).
__device__ uint16_t g_Xh[8388608], g_Xl[8388608];   // X  [8192,1024] (perm)
__device__ uint16_t g_Wh[4194304], g_Wl[4194304];   // Wq,Wk,Wv,Wo    (perm)
__device__ uint16_t g_Qh[8388608], g_Ql[8388608];   // Q  (x0.125 folded, linear)
__device__ uint16_t g_Kh[8388608], g_Kl[8388608];   // K  (linear)
__device__ float    g_V [8388608];                  // V  tf32-rounded fp32
__device__ uint16_t g_Yh[8388608], g_Yl[8388608];   // Y  [B,S,E]     (perm)

// ===========================================================================
// Helpers
// ===========================================================================
__device__ __forceinline__ uint32_t smem_u32(const void* p) {
    uint32_t a;
    asm("{ .reg .u64 t; cvta.to.shared.u64 t, %1; cvt.u32.u64 %0, t; }"
        : "=r"(a) : "l"(p));
    return a;
}
__device__ __forceinline__ void cp_async16(uint32_t s, const void* g) {
    asm volatile("cp.async.cg.shared.global [%0], [%1], 16;" :: "r"(s), "l"(g));
}
__device__ __forceinline__ void cp_commit() {
    asm volatile("cp.async.commit_group;" ::: "memory");
}
template <int N>
__device__ __forceinline__ void cp_wait_group() {
    asm volatile("cp.async.wait_group %0;" :: "n"(N) : "memory");
}
__device__ __forceinline__ void mma_bf16(float* c, const uint32_t* a, const uint32_t* b) {
    asm volatile(
        "mma.sync.aligned.m16n8k16.row.col.f32.bf16.bf16.f32 "
        "{%0,%1,%2,%3}, {%4,%5,%6,%7}, {%8,%9}, {%0,%1,%2,%3};"
        : "+f"(c[0]), "+f"(c[1]), "+f"(c[2]), "+f"(c[3])
        : "r"(a[0]), "r"(a[1]), "r"(a[2]), "r"(a[3]), "r"(b[0]), "r"(b[1]));
}
__device__ __forceinline__ void mma_tf32(float* c, const uint32_t* a, const uint32_t* b) {
    asm volatile(
        "mma.sync.aligned.m16n8k8.row.col.f32.tf32.tf32.f32 "
        "{%0,%1,%2,%3}, {%4,%5,%6,%7}, {%8,%9}, {%0,%1,%2,%3};"
        : "+f"(c[0]), "+f"(c[1]), "+f"(c[2]), "+f"(c[3])
        : "r"(a[0]), "r"(a[1]), "r"(a[2]), "r"(a[3]), "r"(b[0]), "r"(b[1]));
}
__device__ __forceinline__ uint32_t f2tf32(float x) {
    uint32_t r;
    asm("cvt.rna.tf32.f32 %0, %1;" : "=r"(r) : "f"(x));
    return r;
}
__device__ __forceinline__ float rtf(float x) { return __uint_as_float(f2tf32(x)); }

// bf16 split via integer bit ops (RN); lo is an unfoldable exact FSUB.
__device__ __forceinline__ uint32_t bf_rn_bits(float x) {
    const uint32_t b = __float_as_uint(x);
    return (b + 0x7FFFu + ((b >> 16) & 1u)) & 0xFFFF0000u;
}
__device__ __forceinline__ void bf_split(float x, uint16_t& h, uint16_t& l) {
    const uint32_t hb = bf_rn_bits(x);
    h = (uint16_t)(hb >> 16);
    const float lo = x - __uint_as_float(hb);
    l = (uint16_t)(bf_rn_bits(lo) >> 16);
}
// permuted slot (element units) for an even pair base c within its 16-group
__device__ __forceinline__ int perm_pair(int c) {
    return (c & ~15) + (((c >> 1) & 3) << 2) + (((c >> 3) & 1) << 1);
}

// ===========================================================================
// Pre-split fp32 -> bf16 hi/lo planes, column-permuted within 16-groups.
// ===========================================================================
__global__ __launch_bounds__(256) void split_bf(const float4* __restrict__ src,
                                                uint16_t* __restrict__ dh,
                                                uint16_t* __restrict__ dl, int n4)
{
    const int i = blockIdx.x * 256 + threadIdx.x;
    if (i >= n4) return;
    const float4 v = src[i];
    uint16_t h0, h1, h2, h3, l0, l1, l2, l3;
    bf_split(v.x, h0, l0); bf_split(v.y, h1, l1);
    bf_split(v.z, h2, l2); bf_split(v.w, h3, l3);
    const int c0 = (4 * i) & 15;                       // 0,4,8,12
    const int g  = (4 * i) & ~15;                      // group base (global)
    const int m0 = g + (((c0 & 4) << 1) | ((c0 & 8) >> 2));
    *(uint32_t*)&dh[m0]     = (uint32_t)h0 | ((uint32_t)h1 << 16);
    *(uint32_t*)&dh[m0 + 4] = (uint32_t)h2 | ((uint32_t)h3 << 16);
    *(uint32_t*)&dl[m0]     = (uint32_t)l0 | ((uint32_t)l1 << 16);
    *(uint32_t*)&dl[m0 + 4] = (uint32_t)l2 | ((uint32_t)l3 << 16);
}

// ===========================================================================
// 3xbf16 GEMM, permuted planes, LDS.64 fragments. Pitch 96 B/row
// (conflict-free: bank bases {0,24,16,8} per phase). 2 CTAs/SM (98304 B).
// Epilogue: Q/K written LINEAR for flash; V tf32-rounded; out fp32 linear.
// ===========================================================================
#define GPIT   96
#define GPLANE (128 * GPIT)
#define GSTG   (4 * GPLANE)
#define GSMEM2 (2 * GSTG)

template <bool SCATTER>
__global__ __launch_bounds__(256, 2) void gemm_bf(float* __restrict__ outp)
{
    const uint16_t *Aph, *Apl, *Bph, *Bpl;
    if (SCATTER) {
        Aph = g_Xh; Apl = g_Xl;
        Bph = g_Wh + (size_t)blockIdx.z * 1048576;
        Bpl = g_Wl + (size_t)blockIdx.z * 1048576;
    } else {
        Aph = g_Yh; Apl = g_Yl;
        Bph = g_Wh + 3145728; Bpl = g_Wl + 3145728;
    }

    extern __shared__ __align__(16) char smc[];
    const int tid  = threadIdx.x;
    const int wid  = tid >> 5;
    const int lane = tid & 31;
    const int m0   = blockIdx.x * 128;
    const int n0   = blockIdx.y * 128;
    const int wm   = (wid >> 1) * 32;
    const int wn   = (wid & 1) * 64;
    const int q    = lane & 3;
    const int g8   = lane >> 2;
    const uint32_t sbase = smem_u32(smc);

    auto load_stage = [&](int kt, uint32_t soff) {
#pragma unroll
        for (int j = 0; j < 4; j++) {
            const int f = tid + 256 * j;
            const int pl = f >> 9, r = (f >> 2) & 127, c = f & 3;
            const uint16_t* ap = pl ? Apl : Aph;
            cp_async16(sbase + soff + (uint32_t)(pl * GPLANE + r * GPIT + c * 16),
                       ap + ((size_t)(m0 + r)) * 1024 + kt * 32 + c * 8);
        }
#pragma unroll
        for (int j = 0; j < 4; j++) {
            const int f = tid + 256 * j;
            const int pl = f >> 9, r = (f >> 2) & 127, c = f & 3;
            const uint16_t* bp = pl ? Bpl : Bph;
            cp_async16(sbase + soff + (uint32_t)(2 * GPLANE + pl * GPLANE + r * GPIT + c * 16),
                       bp + ((size_t)(n0 + r)) * 1024 + kt * 32 + c * 8);
        }
        cp_commit();
    };

    load_stage(0, 0);

    float acc[2][8][4];
#pragma unroll
    for (int t = 0; t < 2; t++)
#pragma unroll
        for (int u = 0; u < 8; u++)
#pragma unroll
            for (int r = 0; r < 4; r++) acc[t][u][r] = 0.f;

    for (int kt = 0; kt < 32; kt++) {
        if (kt + 1 < 32) {
            load_stage(kt + 1, ((kt + 1) & 1) * (uint32_t)GSTG);
            cp_wait_group<1>();
        } else {
            cp_wait_group<0>();
        }
        __syncthreads();

        const char* stg = smc + (kt & 1) * GSTG;
        const char* Ah = stg;
        const char* Al = stg + GPLANE;
        const char* Bh = stg + 2 * GPLANE;
        const char* Bl = stg + 3 * GPLANE;

#pragma unroll
        for (int ks = 0; ks < 2; ks++) {
            const int kb = ks * 32 + 8 * q;          // permuted: LDS.64 offset
            uint32_t ah[2][4], al[2][4];
#pragma unroll
            for (int t = 0; t < 2; t++) {
                const int r0 = (wm + t * 16 + g8) * GPIT;
                const uint2 vh0 = *(const uint2*)(Ah + r0 + kb);
                const uint2 vh1 = *(const uint2*)(Ah + r0 + 8 * GPIT + kb);
                const uint2 vl0 = *(const uint2*)(Al + r0 + kb);
                const uint2 vl1 = *(const uint2*)(Al + r0 + 8 * GPIT + kb);
                ah[t][0] = vh0.x; ah[t][2] = vh0.y;
                ah[t][1] = vh1.x; ah[t][3] = vh1.y;
                al[t][0] = vl0.x; al[t][2] = vl0.y;
                al[t][1] = vl1.x; al[t][3] = vl1.y;
            }
#pragma unroll
            for (int u = 0; u < 8; u++) {
                const int nb = (wn + u * 8 + g8) * GPIT + kb;
                const uint2 vbh = *(const uint2*)(Bh + nb);
                const uint2 vbl = *(const uint2*)(Bl + nb);
                uint32_t bh[2], bl[2];
                bh[0] = vbh.x; bh[1] = vbh.y;
                bl[0] = vbl.x; bl[1] = vbl.y;
#pragma unroll
                for (int t = 0; t < 2; t++) {
                    mma_bf16(acc[t][u], ah[t], bh);
                    mma_bf16(acc[t][u], ah[t], bl);
                    mma_bf16(acc[t][u], al[t], bh);
                }
            }
        }
        __syncthreads();    // all reads done before next stage overwrite
    }

    // ---- epilogue ----
    const int z = SCATTER ? blockIdx.z : 3;
#pragma unroll
    for (int t = 0; t < 2; t++) {
#pragma unroll
        for (int u = 0; u < 8; u++) {
            const int m = m0 + wm + t * 16 + g8;
            const int n = n0 + wn + u * 8 + q * 2;
#pragma unroll
            for (int hh = 0; hh < 2; hh++) {
                const int mm = m + hh * 8;
                const float v0 = acc[t][u][hh * 2];
                const float v1 = acc[t][u][hh * 2 + 1];
                if (SCATTER) {
                    const int bb = mm >> 11, s = mm & 2047;
                    const int h = n >> 6, d0 = n & 63;
                    const size_t e = (((size_t)bb * NH + h) * S_LEN + s) * DH + d0;
                    if (z == 0) {
                        const float y0 = v0 * 0.125f, y1 = v1 * 0.125f; // exact fold
                        uint16_t h0, l0, h1, l1;
                        bf_split(y0, h0, l0); bf_split(y1, h1, l1);
                        *(uint32_t*)&g_Qh[e] = (uint32_t)h0 | ((uint32_t)h1 << 16);
                        *(uint32_t*)&g_Ql[e] = (uint32_t)l0 | ((uint32_t)l1 << 16);
                    } else if (z == 1) {
                        uint16_t h0, l0, h1, l1;
                        bf_split(v0, h0, l0); bf_split(v1, h1, l1);
                        *(uint32_t*)&g_Kh[e] = (uint32_t)h0 | ((uint32_t)h1 << 16);
                        *(uint32_t*)&g_Kl[e] = (uint32_t)l0 | ((uint32_t)l1 << 16);
                    } else {
                        *(float2*)(g_V + e) = make_float2(rtf(v0), rtf(v1));
                    }
                } else {
                    *(float2*)(outp + (size_t)mm * EMB + n) = make_float2(v0, v1);
                }
            }
        }
    }
}

// ===========================================================================
// Flash attention — ROUND-14 PROVEN kernel verbatim (3xbf16 QK via linear
// planes pitch-144, 1xTF32 PV, race-fixed, LPT, 110592 B = 2 CTAs/SM).
// ONLY change: Y epilogue writes PERMUTED planes for the out-proj gemm.
// ===========================================================================
#define FLASH_SMEM 110592

__global__ __launch_bounds__(256) void flash_mma()
{
    const int bh = blockIdx.x;
    const int qi = 15 - blockIdx.y;          // LPT: long jobs first

    extern __shared__ __align__(16) char smc[];
    float* P = (float*)smc;                   // pitch 68 floats, overlays Q planes

    const int tid  = threadIdx.x;
    const int wid  = tid >> 5;
    const int lane = tid & 31;
    const int g8   = lane >> 2;
    const int q    = lane & 3;
    const int wm   = wid * 16;
    const uint32_t sbase = smem_u32(smc);

    // ---- Q planes (group 0) ----
#pragma unroll
    for (int j = 0; j < 8; j++) {
        const int f = tid + 256 * j;
        const int pl = f >> 10, ff = f & 1023, row = ff >> 3, c = ff & 7;
        const uint16_t* qp = pl ? g_Ql : g_Qh;
        cp_async16(sbase + (uint32_t)(pl * 18432 + row * 144 + c * 16),
                   qp + ((size_t)bh * S_LEN + qi * 128 + row) * 64 + c * 8);
    }
    cp_commit();
    // ---- K planes + V, stage 0 (group 1) ----
#pragma unroll
    for (int j = 0; j < 4; j++) {
        const int f = tid + 256 * j;
        const int pl = f >> 9, ff = f & 511, row = ff >> 3, c = ff & 7;
        const uint16_t* kp = pl ? g_Kl : g_Kh;
        cp_async16(sbase + (uint32_t)(36864 + pl * 9216 + row * 144 + c * 16),
                   kp + ((size_t)bh * S_LEN + row) * 64 + c * 8);
    }
#pragma unroll
    for (int j = 0; j < 4; j++) {
        const int f = tid + 256 * j;
        const int row = f >> 4, c = f & 15;
        cp_async16(sbase + (uint32_t)(73728 + row * 288 + c * 16),
                   g_V + ((size_t)bh * S_LEN + row) * 64 + c * 4);
    }
    cp_commit();

    cp_wait_group<1>();
    __syncthreads();

    // ---- hoist Q fragments (packed bf16, both planes) ----
    uint32_t qh[4][4], ql[4][4];
    {
        const char* Qhp = smc;
        const char* Qlp = smc + 18432;
        const int rb = (wm + g8) * 144;
#pragma unroll
        for (int kc = 0; kc < 4; kc++) {
            const int kb = kc * 32 + 4 * q;
            qh[kc][0] = *(const uint32_t*)(Qhp + rb + kb);
            qh[kc][1] = *(const uint32_t*)(Qhp + rb + 1152 + kb);
            qh[kc][2] = *(const uint32_t*)(Qhp + rb + kb + 16);
            qh[kc][3] = *(const uint32_t*)(Qhp + rb + 1152 + kb + 16);
            ql[kc][0] = *(const uint32_t*)(Qlp + rb + kb);
            ql[kc][1] = *(const uint32_t*)(Qlp + rb + 1152 + kb);
            ql[kc][2] = *(const uint32_t*)(Qlp + rb + kb + 16);
            ql[kc][3] = *(const uint32_t*)(Qlp + rb + 1152 + kb + 16);
        }
    }
    __syncthreads();                          // Q reads done before P stores

    float m0 = -1e30f, m1 = -1e30f, l0 = 0.f, l1 = 0.f;
    float o[8][4];
#pragma unroll
    for (int u = 0; u < 8; u++)
#pragma unroll
        for (int r = 0; r < 4; r++) o[u][r] = 0.f;

    const int row0 = qi * 128 + wm + g8;
    const int row1 = row0 + 8;
    const int last = 2 * qi + 1;

    for (int kt = 0; kt <= last; kt++) {
        if (kt < last) {
            const int st = (kt + 1) & 1;
            const size_t kbase = (size_t)bh * S_LEN + (size_t)(kt + 1) * 64;
#pragma unroll
            for (int j = 0; j < 4; j++) {
                const int f = tid + 256 * j;
                const int pl = f >> 9, ff = f & 511, row = ff >> 3, c = ff & 7;
                const uint16_t* kp = pl ? g_Kl : g_Kh;
                cp_async16(sbase + (uint32_t)(36864 + st * 18432 + pl * 9216 + row * 144 + c * 16),
                           kp + (kbase + row) * 64 + c * 8);
            }
#pragma unroll
            for (int j = 0; j < 4; j++) {
                const int f = tid + 256 * j;
                const int row = f >> 4, c = f & 15;
                cp_async16(sbase + (uint32_t)(73728 + st * 18432 + row * 288 + c * 16),
                           g_V + (kbase + row) * 64 + c * 4);
            }
            cp_commit();
            cp_wait_group<1>();
        } else {
            cp_wait_group<0>();
        }
        __syncthreads();

        const char* Khp = smc + 36864 + (kt & 1) * 18432;
        const char* Klp = Khp + 9216;
        const float* Vst = (const float*)(smc + 73728 + (kt & 1) * 18432);

        // ---- S = Q K^T (3xbf16, scale pre-folded, ALU-free) ----
        float s[8][4];
#pragma unroll
        for (int u = 0; u < 8; u++)
#pragma unroll
            for (int r = 0; r < 4; r++) s[u][r] = 0.f;

#pragma unroll
        for (int kc = 0; kc < 4; kc++) {
#pragma unroll
            for (int u = 0; u < 8; u++) {
                const int nb = (u * 8 + g8) * 144 + kc * 32 + 4 * q;
                uint32_t bh2[2], bl2[2];
                bh2[0] = *(const uint32_t*)(Khp + nb);
                bh2[1] = *(const uint32_t*)(Khp + nb + 16);
                bl2[0] = *(const uint32_t*)(Klp + nb);
                bl2[1] = *(const uint32_t*)(Klp + nb + 16);
                mma_bf16(s[u], qh[kc], bh2);
                mma_bf16(s[u], qh[kc], bl2);
                mma_bf16(s[u], ql[kc], bh2);
            }
        }

        // causal mask (diagonal tiles only)
        if (kt >= 2 * qi) {
            const int cb = kt * 64;
#pragma unroll
            for (int u = 0; u < 8; u++) {
                const int c = cb + u * 8 + 2 * q;
                if (c     > row0) s[u][0] = -1e30f;
                if (c + 1 > row0) s[u][1] = -1e30f;
                if (c     > row1) s[u][2] = -1e30f;
                if (c + 1 > row1) s[u][3] = -1e30f;
            }
        }

        // ---- online softmax (quad reduction) ----
        float tm0 = -1e30f, tm1 = -1e30f;
#pragma unroll
        for (int u = 0; u < 8; u++) {
            tm0 = fmaxf(tm0, fmaxf(s[u][0], s[u][1]));
            tm1 = fmaxf(tm1, fmaxf(s[u][2], s[u][3]));
        }
        tm0 = fmaxf(tm0, __shfl_xor_sync(0xffffffffu, tm0, 1));
        tm0 = fmaxf(tm0, __shfl_xor_sync(0xffffffffu, tm0, 2));
        tm1 = fmaxf(tm1, __shfl_xor_sync(0xffffffffu, tm1, 1));
        tm1 = fmaxf(tm1, __shfl_xor_sync(0xffffffffu, tm1, 2));

        const float mn0 = fmaxf(m0, tm0);
        const float mn1 = fmaxf(m1, tm1);
        const float a0 = __expf(m0 - mn0);
        const float a1 = __expf(m1 - mn1);

        float ps0 = 0.f, ps1 = 0.f;
#pragma unroll
        for (int u = 0; u < 8; u++) {
            const float p00 = __expf(s[u][0] - mn0);
            const float p01 = __expf(s[u][1] - mn0);
            const float p10 = __expf(s[u][2] - mn1);
            const float p11 = __expf(s[u][3] - mn1);
            ps0 += p00 + p01;
            ps1 += p10 + p11;
            *(float2*)&P[(wm + g8) * 68 + u * 8 + 2 * q]     = make_float2(p00, p01);
            *(float2*)&P[(wm + g8 + 8) * 68 + u * 8 + 2 * q] = make_float2(p10, p11);
        }
        ps0 += __shfl_xor_sync(0xffffffffu, ps0, 1);
        ps0 += __shfl_xor_sync(0xffffffffu, ps0, 2);
        ps1 += __shfl_xor_sync(0xffffffffu, ps1, 1);
        ps1 += __shfl_xor_sync(0xffffffffu, ps1, 2);

        l0 = l0 * a0 + ps0;
        l1 = l1 * a1 + ps1;
        m0 = mn0;
        m1 = mn1;
#pragma unroll
        for (int u = 0; u < 8; u++) {
            o[u][0] *= a0; o[u][1] *= a0;
            o[u][2] *= a1; o[u][3] *= a1;
        }
        __syncwarp();   // P visible within warp

        // ---- O += P @ V (1xTF32; V pre-rounded) ----
#pragma unroll
        for (int kc = 0; kc < 8; kc++) {
            uint32_t a[4];
            a[0] = f2tf32(P[(wm + g8) * 68 + kc * 8 + q]);
            a[1] = f2tf32(P[(wm + g8 + 8) * 68 + kc * 8 + q]);
            a[2] = f2tf32(P[(wm + g8) * 68 + kc * 8 + q + 4]);
            a[3] = f2tf32(P[(wm + g8 + 8) * 68 + kc * 8 + q + 4]);
#pragma unroll
            for (int u = 0; u < 8; u++) {
                uint32_t b[2];
                b[0] = __float_as_uint(Vst[(kc * 8 + q) * 72 + u * 8 + g8]);
                b[1] = __float_as_uint(Vst[(kc * 8 + q + 4) * 72 + u * 8 + g8]);
                mma_tf32(o[u], a, b);
            }
        }

        __syncthreads();   // RACE FIX: all warps done reading stage kt&1
                           // before anyone issues next cp.async into it
    }

    // ---- epilogue: normalize, write Y as PERMUTED bf16 planes ----
    const int b = bh >> 4, h = bh & 15;
    const float i0 = 1.0f / l0;
    const float i1 = 1.0f / l1;
#pragma unroll
    for (int u = 0; u < 8; u++) {
        const int c = u * 8 + 2 * q;
        const int mp = perm_pair(c);
        const size_t e0 = ((size_t)b * S_LEN + row0) * EMB + h * 64 + mp;
        const size_t e1 = ((size_t)b * S_LEN + row1) * EMB + h * 64 + mp;
        const float y0 = o[u][0] * i0, y1 = o[u][1] * i0;
        const float y2 = o[u][2] * i1, y3 = o[u][3] * i1;
        uint16_t h0, lo0, h1, lo1, h2, lo2, h3, lo3;
        bf_split(y0, h0, lo0); bf_split(y1, h1, lo1);
        bf_split(y2, h2, lo2); bf_split(y3, h3, lo3);
        *(uint32_t*)&g_Yh[e0] = (uint32_t)h0 | ((uint32_t)h1 << 16);
        *(uint32_t*)&g_Yl[e0] = (uint32_t)lo0 | ((uint32_t)lo1 << 16);
        *(uint32_t*)&g_Yh[e1] = (uint32_t)h2 | ((uint32_t)h3 << 16);
        *(uint32_t*)&g_Yl[e1] = (uint32_t)lo2 | ((uint32_t)lo3 << 16);
    }
}

// ---------------------------------------------------------------------------
extern "C" void kernel_launch(void* const* d_in, const int* in_sizes, int n_in,
                              void* d_out, int out_size)
{
    (void)in_sizes; (void)n_in; (void)out_size;
    const float* x  = (const float*)d_in[0];
    const float* Wq = (const float*)d_in[1];
    const float* Wk = (const float*)d_in[2];
    const float* Wv = (const float*)d_in[3];
    const float* Wo = (const float*)d_in[4];
    float* out = (float*)d_out;

    static bool attr_done = false;       // idempotent setup (not a work guard)
    static uint16_t *pXh, *pXl, *pWh, *pWl;
    if (!attr_done) {
        cudaFuncSetAttribute(gemm_bf<true>,
                             cudaFuncAttributeMaxDynamicSharedMemorySize, GSMEM2);
        cudaFuncSetAttribute(gemm_bf<false>,
                             cudaFuncAttributeMaxDynamicSharedMemorySize, GSMEM2);
        cudaFuncSetAttribute(flash_mma,
                             cudaFuncAttributeMaxDynamicSharedMemorySize, FLASH_SMEM);
        cudaGetSymbolAddress((void**)&pXh, g_Xh);
        cudaGetSymbolAddress((void**)&pXl, g_Xl);
        cudaGetSymbolAddress((void**)&pWh, g_Wh);
        cudaGetSymbolAddress((void**)&pWl, g_Wl);
        attr_done = true;
    }

    // 0) split X and weights into permuted bf16 hi/lo planes
    split_bf<<<8192, 256>>>((const float4*)x,  pXh, pXl, 2097152);
    split_bf<<<1024, 256>>>((const float4*)Wq, pWh,           pWl,           262144);
    split_bf<<<1024, 256>>>((const float4*)Wk, pWh + 1048576, pWl + 1048576, 262144);
    split_bf<<<1024, 256>>>((const float4*)Wv, pWh + 2097152, pWl + 2097152, 262144);
    split_bf<<<1024, 256>>>((const float4*)Wo, pWh + 3145728, pWl + 3145728, 262144);
    // 1) QKV projections (3xbf16, LDS.64 fragments; Q/K written linear)
    gemm_bf<true><<<dim3(64, 8, 3), 256, GSMEM2>>>(nullptr);
    // 2) Causal flash attention (round-14 PROVEN kernel; Y written permuted)
    flash_mma<<<dim3(64, 16), 256, FLASH_SMEM>>>();
    // 3) Output projection (3xbf16, permuted A/B)
    gemm_bf<false><<<dim3(64, 8), 256, GSMEM2>>>(out);
}